// round 8
// baseline (speedup 1.0000x reference)
#include <cuda_runtime.h>
#include <math.h>
#include <stdint.h>

#define BATCH   32
#define DMODEL  4096
#define NH      32
#define NKV     8
#define GSZ     4          // NH / NKV
#define HD      128
#define QKV_COLS 6144      // (NH + 2*NKV) * HD
#define PBLOCK  64
#define NBLK    64
#define SPLITS  8
#define SPLIT_LEN 512      // 4096 / SPLITS
#define NSUB    SPLITS     // per-CTA merged partials
#define KSPLIT  16
#define KCHUNK  256        // 4096 / KSPLIT

typedef unsigned long long u64;

// -------------------- packed f32x2 helpers (sm_100+) ------------------------
__device__ __forceinline__ u64 ffma2(u64 a, u64 b, u64 c) {
    u64 d;
    asm("fma.rn.f32x2 %0, %1, %2, %3;" : "=l"(d) : "l"(a), "l"(b), "l"(c));
    return d;
}
__device__ __forceinline__ u64 pack2(float lo, float hi) {
    u64 r;
    asm("mov.b64 %0, {%1, %2};" : "=l"(r) : "f"(lo), "f"(hi));
    return r;
}
__device__ __forceinline__ float2 unpack2(u64 v) {
    float2 f;
    asm("mov.b64 {%0, %1}, %2;" : "=f"(f.x), "=f"(f.y) : "l"(v));
    return f;
}
union F4 {
    float4 f4;
    struct { u64 lo, hi; } u;
};

// ------------------------------ scratch -------------------------------------
__device__ float g_qkv_part[KSPLIT][BATCH][QKV_COLS];   // 12.6 MB
__device__ float g_q[BATCH][NH][HD];                    // prescaled by 1/sqrt(HD)
__device__ float g_knew[BATCH][NKV][HD];
__device__ float g_vnew[BATCH][NKV][HD];
__device__ float g_po[BATCH][NKV][GSZ][NSUB][HD];       // 4.2 MB
__device__ float g_pm[BATCH][NKV][GSZ][NSUB];
__device__ float g_pl[BATCH][NKV][GSZ][NSUB];
__device__ float g_attn[BATCH][NH * HD];
__device__ float g_out_part[KSPLIT][BATCH][DMODEL];     // 8.4 MB

// --------------------- K-split 32-row GEMM:  part[s] = x_chunk @ w_chunk ----
__global__ __launch_bounds__(128) void gemm32(const float* __restrict__ x,
                                              const float* __restrict__ w,
                                              float* __restrict__ part,
                                              int ncols) {
    __shared__ float hs[BATCH][KCHUNK];                 // 32 KB
    const int col = blockIdx.x * 128 + threadIdx.x;
    const int k0  = blockIdx.y * KCHUNK;

    for (int i = threadIdx.x; i < BATCH * (KCHUNK / 4); i += 128) {
        int b  = i >> 6;
        int kk = i & 63;
        ((float4*)hs[b])[kk] = ((const float4*)(x + (size_t)b * DMODEL + k0))[kk];
    }
    __syncthreads();

    u64 acc2[BATCH];
#pragma unroll
    for (int b = 0; b < BATCH; b++) acc2[b] = 0ULL;

    const float* wp = w + (size_t)k0 * ncols + col;
#pragma unroll 2
    for (int k = 0; k < KCHUNK; k += 4) {
        float w0 = wp[(size_t)(k + 0) * ncols];
        float w1 = wp[(size_t)(k + 1) * ncols];
        float w2 = wp[(size_t)(k + 2) * ncols];
        float w3 = wp[(size_t)(k + 3) * ncols];
        u64 w01 = pack2(w0, w1);
        u64 w23 = pack2(w2, w3);
#pragma unroll
        for (int b = 0; b < BATCH; b++) {
            F4 h;
            h.f4 = *(const float4*)&hs[b][k];
            acc2[b] = ffma2(h.u.lo, w01, ffma2(h.u.hi, w23, acc2[b]));
        }
    }
    float* op = part + ((size_t)blockIdx.y * BATCH) * ncols + col;
#pragma unroll
    for (int b = 0; b < BATCH; b++) {
        float2 f = unpack2(acc2[b]);
        op[(size_t)b * ncols] = f.x + f.y;
    }
}

// ----------------- reduce k-splits of QKV + RoPE + split q/k/v --------------
__global__ __launch_bounds__(256) void rope_reduce(const int* __restrict__ pos_ids) {
    int idx = blockIdx.x * 256 + threadIdx.x;
    int j  = idx & 63;
    int hh = (idx >> 6) % 48;
    int b  = idx / (48 * 64);

    int c1 = hh * HD + j;
    int c2 = c1 + 64;
    float x1 = 0.f, x2 = 0.f;
#pragma unroll
    for (int s = 0; s < KSPLIT; s++) {
        x1 += g_qkv_part[s][b][c1];
        x2 += g_qkv_part[s][b][c2];
    }
    if (hh < 40) {
        float invf = exp2f(-(float)j * (19.931568569324174f / 64.f)); // 1e6^(-j/64)
        float ang  = (float)pos_ids[b] * invf;
        float c = cosf(ang), s = sinf(ang);
        float y1 = x1 * c - x2 * s;
        float y2 = x2 * c + x1 * s;
        if (hh < 32) {
            const float sc = 0.08838834764831845f;   // 1/sqrt(128)
            g_q[b][hh][j]      = y1 * sc;
            g_q[b][hh][j + 64] = y2 * sc;
        } else {
            g_knew[b][hh - 32][j]      = y1;
            g_knew[b][hh - 32][j + 64] = y2;
        }
    } else {
        g_vnew[b][hh - 40][j]      = x1;
        g_vnew[b][hh - 40][j + 64] = x2;
    }
}

// ------------- per-warp two-phase split-KV flash-decode ----------------------
// grid: (SPLITS, NKV, BATCH), block 256 (8 warps), 3 CTAs/SM.
// Hot loops are branch-free affine streams over the (stale) cache; the single
// position holding the new token is patched AFTER each loop:
//   scores : recompute that slot's dot product with k_new (overwrite pre-exp;
//            a stale-inflated running max only rescales softmax consistently)
//   V pass : acc += p[slot] * (v_new - v_stale)
__global__ __launch_bounds__(256, 3) void attn_split(const float* __restrict__ kc,
                                                     const float* __restrict__ vc,
                                                     const int* __restrict__ btab,
                                                     const int* __restrict__ seqlens) {
    const int s   = blockIdx.x;
    const int kvh = blockIdx.y;
    const int b   = blockIdx.z;

    __shared__ float4 ps4[8][PBLOCK];       // 8 KB: per-warp scores/probs (g-packed)
    __shared__ float  red[8][GSZ][HD];      // 16 KB: per-warp V partials
    __shared__ float  sm_m[8][GSZ], sm_l[8][GSZ];

    const int t    = threadIdx.x;
    const int w    = t >> 5;
    const int lane = t & 31;
    const int kvlen  = seqlens[b];
    const int newpos = kvlen - 1;

    const int phys = btab[b * NBLK + s * 8 + w];
    const int lsub = lane >> 3;      // octet index (position group)
    const int dch  = lane & 7;       // 16-dim chunk within octet

    const float* kblock = kc + ((size_t)phys * PBLOCK) * NKV * HD + (size_t)kvh * HD;
    const float* vblock = vc + ((size_t)phys * PBLOCK) * NKV * HD + (size_t)kvh * HD;
    const int base = s * SPLIT_LEN + w * 64;
    const int fixslot = newpos - base;       // in [0,64) for exactly one warp

    float mloc[GSZ];
    // ---------------- phase A: scores -> smem (branch-free stream) ----------
    {
        F4 qr[GSZ][4];
#pragma unroll
        for (int g = 0; g < GSZ; g++) {
            const float4* qp = (const float4*)&g_q[b][kvh * GSZ + g][0];
#pragma unroll
            for (int q = 0; q < 4; q++) qr[g][q].f4 = qp[dch * 4 + q];
        }
#pragma unroll
        for (int g = 0; g < GSZ; g++) mloc[g] = -1e30f;

#pragma unroll 2
        for (int i = 0; i < 16; i++) {
            const int slot = i * 4 + lsub;
            const float* kp = kblock + (size_t)slot * NKV * HD;

            F4 kv[4];
#pragma unroll
            for (int q = 0; q < 4; q++) kv[q].f4 = __ldcs(((const float4*)kp) + dch * 4 + q);

            float sg[GSZ];
#pragma unroll
            for (int g = 0; g < GSZ; g++) {
                u64 a2 = 0ULL;
#pragma unroll
                for (int q = 0; q < 4; q++) {
                    a2 = ffma2(qr[g][q].u.lo, kv[q].u.lo, a2);
                    a2 = ffma2(qr[g][q].u.hi, kv[q].u.hi, a2);
                }
                float2 f = unpack2(a2);
                sg[g] = f.x + f.y;
            }
#pragma unroll
            for (int off = 1; off < 8; off <<= 1)
#pragma unroll
                for (int g = 0; g < GSZ; g++)
                    sg[g] += __shfl_xor_sync(0xffffffff, sg[g], off);

            if (dch == 0) {
                const bool valid = (base + slot) < kvlen;
                float4 sv;
                sv.x = valid ? sg[0] : -1e30f;
                sv.y = valid ? sg[1] : -1e30f;
                sv.z = valid ? sg[2] : -1e30f;
                sv.w = valid ? sg[3] : -1e30f;
                ps4[w][slot] = sv;
                mloc[0] = fmaxf(mloc[0], sv.x);
                mloc[1] = fmaxf(mloc[1], sv.y);
                mloc[2] = fmaxf(mloc[2], sv.z);
                mloc[3] = fmaxf(mloc[3], sv.w);
            }
        }

        // ---- patch the new-token slot (at most one warp per batch b) ----
        if (fixslot >= 0 && fixslot < 64) {
            const float4* kp = (const float4*)&g_knew[b][kvh][0];
            F4 kv[4];
#pragma unroll
            for (int q = 0; q < 4; q++) kv[q].f4 = kp[dch * 4 + q];
            float sg[GSZ];
#pragma unroll
            for (int g = 0; g < GSZ; g++) {
                u64 a2 = 0ULL;
#pragma unroll
                for (int q = 0; q < 4; q++) {
                    a2 = ffma2(qr[g][q].u.lo, kv[q].u.lo, a2);
                    a2 = ffma2(qr[g][q].u.hi, kv[q].u.hi, a2);
                }
                float2 f = unpack2(a2);
                sg[g] = f.x + f.y;
            }
#pragma unroll
            for (int off = 1; off < 8; off <<= 1)
#pragma unroll
                for (int g = 0; g < GSZ; g++)
                    sg[g] += __shfl_xor_sync(0xffffffff, sg[g], off);
            if (dch == 0) {
                float4 sv = make_float4(sg[0], sg[1], sg[2], sg[3]);
                ps4[w][fixslot] = sv;
                mloc[0] = fmaxf(mloc[0], sv.x);
                mloc[1] = fmaxf(mloc[1], sv.y);
                mloc[2] = fmaxf(mloc[2], sv.z);
                mloc[3] = fmaxf(mloc[3], sv.w);
            }
        }

#pragma unroll
        for (int off = 16; off >= 1; off >>= 1)
#pragma unroll
            for (int g = 0; g < GSZ; g++)
                mloc[g] = fmaxf(mloc[g], __shfl_xor_sync(0xffffffff, mloc[g], off));
        __syncwarp();
    }

    // ---------------- phase B: exp + l ----------------
    {
        float4 s0 = ps4[w][lane];
        float4 s1 = ps4[w][lane + 32];
        float4 p0, p1;
        p0.x = __expf(s0.x - mloc[0]); p1.x = __expf(s1.x - mloc[0]);
        p0.y = __expf(s0.y - mloc[1]); p1.y = __expf(s1.y - mloc[1]);
        p0.z = __expf(s0.z - mloc[2]); p1.z = __expf(s1.z - mloc[2]);
        p0.w = __expf(s0.w - mloc[3]); p1.w = __expf(s1.w - mloc[3]);
        ps4[w][lane] = p0;
        ps4[w][lane + 32] = p1;
        float l0 = p0.x + p1.x, l1 = p0.y + p1.y;
        float l2 = p0.z + p1.z, l3 = p0.w + p1.w;
#pragma unroll
        for (int off = 16; off >= 1; off >>= 1) {
            l0 += __shfl_xor_sync(0xffffffff, l0, off);
            l1 += __shfl_xor_sync(0xffffffff, l1, off);
            l2 += __shfl_xor_sync(0xffffffff, l2, off);
            l3 += __shfl_xor_sync(0xffffffff, l3, off);
        }
        if (lane == 0) {
            sm_m[w][0] = mloc[0]; sm_m[w][1] = mloc[1];
            sm_m[w][2] = mloc[2]; sm_m[w][3] = mloc[3];
            sm_l[w][0] = l0; sm_l[w][1] = l1; sm_l[w][2] = l2; sm_l[w][3] = l3;
        }
        __syncwarp();
    }

    // -------- phase C: V stream (branch-free), patch afterwards ------------
    {
        u64 acc2[GSZ][2];
#pragma unroll
        for (int g = 0; g < GSZ; g++) { acc2[g][0] = 0ULL; acc2[g][1] = 0ULL; }

#pragma unroll 8
        for (int slot = 0; slot < 64; slot++) {
            F4 v4;
            v4.f4 = __ldcs(((const float4*)(vblock + (size_t)slot * NKV * HD)) + lane);
            float4 p4 = ps4[w][slot];            // smem broadcast
            u64 pa = pack2(p4.x, p4.x);
            u64 pb = pack2(p4.y, p4.y);
            u64 pc = pack2(p4.z, p4.z);
            u64 pd = pack2(p4.w, p4.w);
            acc2[0][0] = ffma2(pa, v4.u.lo, acc2[0][0]);
            acc2[0][1] = ffma2(pa, v4.u.hi, acc2[0][1]);
            acc2[1][0] = ffma2(pb, v4.u.lo, acc2[1][0]);
            acc2[1][1] = ffma2(pb, v4.u.hi, acc2[1][1]);
            acc2[2][0] = ffma2(pc, v4.u.lo, acc2[2][0]);
            acc2[2][1] = ffma2(pc, v4.u.hi, acc2[2][1]);
            acc2[3][0] = ffma2(pd, v4.u.lo, acc2[3][0]);
            acc2[3][1] = ffma2(pd, v4.u.hi, acc2[3][1]);
        }

        // ---- patch: acc += p[fixslot] * (v_new - v_stale) ----
        if (fixslot >= 0 && fixslot < 64) {
            float4 vst = ((const float4*)(vblock + (size_t)fixslot * NKV * HD))[lane];
            float4 vnw = ((const float4*)&g_vnew[b][kvh][0])[lane];
            F4 dv;
            dv.f4 = make_float4(vnw.x - vst.x, vnw.y - vst.y,
                                vnw.z - vst.z, vnw.w - vst.w);
            float4 p4 = ps4[w][fixslot];
            u64 pa = pack2(p4.x, p4.x);
            u64 pb = pack2(p4.y, p4.y);
            u64 pc = pack2(p4.z, p4.z);
            u64 pd = pack2(p4.w, p4.w);
            acc2[0][0] = ffma2(pa, dv.u.lo, acc2[0][0]);
            acc2[0][1] = ffma2(pa, dv.u.hi, acc2[0][1]);
            acc2[1][0] = ffma2(pb, dv.u.lo, acc2[1][0]);
            acc2[1][1] = ffma2(pb, dv.u.hi, acc2[1][1]);
            acc2[2][0] = ffma2(pc, dv.u.lo, acc2[2][0]);
            acc2[2][1] = ffma2(pc, dv.u.hi, acc2[2][1]);
            acc2[3][0] = ffma2(pd, dv.u.lo, acc2[3][0]);
            acc2[3][1] = ffma2(pd, dv.u.hi, acc2[3][1]);
        }

#pragma unroll
        for (int g = 0; g < GSZ; g++) {
            F4 o;
            o.u.lo = acc2[g][0];
            o.u.hi = acc2[g][1];
            ((float4*)&red[w][g][0])[lane] = o.f4;
        }
    }
    __syncthreads();

    // -------- epilogue: flash-merge the 8 warps' partials -> one ----------
#pragma unroll
    for (int rep = 0; rep < 2; rep++) {
        int idx = t + rep * 256;
        int g = idx >> 7, d = idx & 127;
        float M = sm_m[0][g];
#pragma unroll
        for (int ww = 1; ww < 8; ww++) M = fmaxf(M, sm_m[ww][g]);
        float o = 0.f;
#pragma unroll
        for (int ww = 0; ww < 8; ww++)
            o += __expf(sm_m[ww][g] - M) * red[ww][g][d];
        g_po[b][kvh][g][s][d] = o;
        if (d == 0) {
            float L = 0.f;
#pragma unroll
            for (int ww = 0; ww < 8; ww++)
                L += __expf(sm_m[ww][g] - M) * sm_l[ww][g];
            g_pm[b][kvh][g][s] = M;
            g_pl[b][kvh][g][s] = L;
        }
    }
}

// ----------------------- combine split partials -----------------------------
__global__ __launch_bounds__(128) void combine_splits() {
    const int bh = blockIdx.x;
    const int b = bh >> 5, h = bh & 31;
    const int kvh = h >> 2, g = h & 3;
    const int d = threadIdx.x;

    float m = -1e30f;
#pragma unroll
    for (int s = 0; s < NSUB; s++) m = fmaxf(m, g_pm[b][kvh][g][s]);
    float denom = 0.f, o = 0.f;
#pragma unroll
    for (int s = 0; s < NSUB; s++) {
        float e = __expf(g_pm[b][kvh][g][s] - m);
        denom += e * g_pl[b][kvh][g][s];
        o += e * g_po[b][kvh][g][s][d];
    }
    g_attn[b][h * HD + d] = o / denom;
}

// ----------------------- final k-split reduce -------------------------------
__global__ __launch_bounds__(256) void final_reduce(float* __restrict__ out) {
    int e = blockIdx.x * 256 + threadIdx.x;        // over 32*4096
    const float* p = &g_out_part[0][0][0];
    float sum = 0.f;
#pragma unroll
    for (int s = 0; s < KSPLIT; s++) sum += p[(size_t)s * BATCH * DMODEL + e];
    out[e] = sum;
}

// ---------------------------------------------------------------------------
extern "C" void kernel_launch(void* const* d_in, const int* in_sizes, int n_in,
                              void* d_out, int out_size) {
    const float* hid  = (const float*)d_in[0];
    const float* wqkv = (const float*)d_in[1];
    const float* wo   = (const float*)d_in[2];
    const float* kc   = (const float*)d_in[3];
    const float* vc   = (const float*)d_in[4];
    const int*   pos  = (const int*)d_in[5];
    const int*   btab = (const int*)d_in[6];
    const int*   slen = (const int*)d_in[7];
    float* out = (float*)d_out;

    void *p_qkv_part, *p_attn, *p_out_part;
    cudaGetSymbolAddress(&p_qkv_part, g_qkv_part);
    cudaGetSymbolAddress(&p_attn, g_attn);
    cudaGetSymbolAddress(&p_out_part, g_out_part);

    gemm32<<<dim3(QKV_COLS / 128, KSPLIT), 128>>>(hid, wqkv, (float*)p_qkv_part, QKV_COLS);
    rope_reduce<<<(BATCH * 48 * 64) / 256, 256>>>(pos);
    attn_split<<<dim3(SPLITS, NKV, BATCH), 256>>>(kc, vc, btab, slen);
    combine_splits<<<BATCH * NH, 128>>>();
    gemm32<<<dim3(DMODEL / 128, KSPLIT), 128>>>((const float*)p_attn, wo, (float*)p_out_part, DMODEL);
    final_reduce<<<(BATCH * DMODEL) / 256, 256>>>(out);
}

// round 9
// speedup vs baseline: 1.1588x; 1.1588x over previous
#include <cuda_runtime.h>
#include <math.h>
#include <stdint.h>

#define BATCH   32
#define DMODEL  4096
#define NH      32
#define NKV     8
#define GSZ     4          // NH / NKV
#define HD      128
#define QKV_COLS 6144      // (NH + 2*NKV) * HD
#define PBLOCK  64
#define NBLK    64
#define SPLITS  8
#define SPLIT_LEN 512      // 4096 / SPLITS
#define NSUB    SPLITS     // per-CTA merged partials
#define KSPLIT  16
#define KCHUNK  256        // 4096 / KSPLIT
#define GK      16         // gemm k-tile rows

typedef unsigned long long u64;

// -------------------- packed f32x2 helpers (sm_100+) ------------------------
__device__ __forceinline__ u64 ffma2(u64 a, u64 b, u64 c) {
    u64 d;
    asm("fma.rn.f32x2 %0, %1, %2, %3;" : "=l"(d) : "l"(a), "l"(b), "l"(c));
    return d;
}
__device__ __forceinline__ u64 pack2(float lo, float hi) {
    u64 r;
    asm("mov.b64 %0, {%1, %2};" : "=l"(r) : "f"(lo), "f"(hi));
    return r;
}
__device__ __forceinline__ float2 unpack2(u64 v) {
    float2 f;
    asm("mov.b64 {%0, %1}, %2;" : "=f"(f.x), "=f"(f.y) : "l"(v));
    return f;
}
union F4 {
    float4 f4;
    struct { u64 lo, hi; } u;
};

// -------------------- tf32 split (3xTF32 compensation) ----------------------
__device__ __forceinline__ void tf32_split(float f, uint32_t& h, uint32_t& l) {
    asm("cvt.rna.tf32.f32 %0, %1;" : "=r"(h) : "f"(f));
    float r = f - __uint_as_float(h);
    asm("cvt.rna.tf32.f32 %0, %1;" : "=r"(l) : "f"(r));
}

#define MMA_TF32(C, A, b0, b1)                                              \
    asm volatile("mma.sync.aligned.m16n8k8.row.col.f32.tf32.tf32.f32 "      \
                 "{%0,%1,%2,%3}, {%4,%5,%6,%7}, {%8,%9}, {%0,%1,%2,%3};"    \
                 : "+f"((C)[0]), "+f"((C)[1]), "+f"((C)[2]), "+f"((C)[3])   \
                 : "r"((A)[0]), "r"((A)[1]), "r"((A)[2]), "r"((A)[3]),      \
                   "r"(b0), "r"(b1))

// ------------------------------ scratch -------------------------------------
__device__ float g_qkv_part[KSPLIT][BATCH][QKV_COLS];   // 12.6 MB
__device__ float g_q[BATCH][NH][HD];                    // prescaled by 1/sqrt(HD)
__device__ float g_knew[BATCH][NKV][HD];
__device__ float g_vnew[BATCH][NKV][HD];
__device__ float g_po[BATCH][NKV][GSZ][NSUB][HD];       // 4.2 MB
__device__ float g_pm[BATCH][NKV][GSZ][NSUB];
__device__ float g_pl[BATCH][NKV][GSZ][NSUB];
__device__ float g_attn[BATCH][NH * HD];
__device__ float g_out_part[KSPLIT][BATCH][DMODEL];     // 8.4 MB

// ----------------- TF32 tensor-core 32-row GEMM (3xTF32) --------------------
// part[s] = x[:, ks] @ w[ks, :] with fp32-grade accuracy via hi/lo split.
// grid: (ncols/128, KSPLIT), block 256 (8 warps, 16 cols each).
// Dynamic smem: xs hi/lo [32][257] + w tile hi/lo [GK][132].
#define XS_PAD 257
#define WB_PAD 132
__global__ __launch_bounds__(256) void gemm_tf32(const float* __restrict__ x,
                                                 const float* __restrict__ w,
                                                 float* __restrict__ part,
                                                 int ncols) {
    extern __shared__ uint32_t dyn[];
    uint32_t* xsh = dyn;                       // 32*257
    uint32_t* xsl = xsh + 32 * XS_PAD;
    uint32_t* wbh = xsl + 32 * XS_PAD;         // GK*132
    uint32_t* wbl = wbh + GK * WB_PAD;

    const int t    = threadIdx.x;
    const int wid  = t >> 5;
    const int lane = t & 31;
    const int g    = lane >> 2;     // groupID 0..7
    const int tq   = lane & 3;      // threadID-in-group 0..3
    const int colbase = blockIdx.x * 128;
    const int k0      = blockIdx.y * KCHUNK;

    // stage x chunk (hi/lo tf32)
    for (int i = t; i < 32 * (KCHUNK / 4); i += 256) {
        int row = i >> 6;
        int kk  = (i & 63) * 4;
        float4 v = *(const float4*)(x + (size_t)row * DMODEL + k0 + kk);
        uint32_t h, l;
        tf32_split(v.x, h, l); xsh[row * XS_PAD + kk + 0] = h; xsl[row * XS_PAD + kk + 0] = l;
        tf32_split(v.y, h, l); xsh[row * XS_PAD + kk + 1] = h; xsl[row * XS_PAD + kk + 1] = l;
        tf32_split(v.z, h, l); xsh[row * XS_PAD + kk + 2] = h; xsl[row * XS_PAD + kk + 2] = l;
        tf32_split(v.w, h, l); xsh[row * XS_PAD + kk + 3] = h; xsl[row * XS_PAD + kk + 3] = l;
    }

    float c[2][2][4];
#pragma unroll
    for (int m = 0; m < 2; m++)
#pragma unroll
        for (int n = 0; n < 2; n++)
#pragma unroll
            for (int j = 0; j < 4; j++) c[m][n][j] = 0.f;

    const int wr0 = t >> 5;          // 0..7 (w staging row)
    const int wcc = (t & 31) * 4;    // 0..124

    for (int it = 0; it < KCHUNK / GK; it++) {
        // stage w tile [GK][128] hi/lo
#pragma unroll
        for (int half = 0; half < 2; half++) {
            int rr = wr0 + half * 8;
            float4 v = *(const float4*)(w + (size_t)(k0 + it * GK + rr) * ncols + colbase + wcc);
            uint32_t h, l;
            tf32_split(v.x, h, l); wbh[rr * WB_PAD + wcc + 0] = h; wbl[rr * WB_PAD + wcc + 0] = l;
            tf32_split(v.y, h, l); wbh[rr * WB_PAD + wcc + 1] = h; wbl[rr * WB_PAD + wcc + 1] = l;
            tf32_split(v.z, h, l); wbh[rr * WB_PAD + wcc + 2] = h; wbl[rr * WB_PAD + wcc + 2] = l;
            tf32_split(v.w, h, l); wbh[rr * WB_PAD + wcc + 3] = h; wbl[rr * WB_PAD + wcc + 3] = l;
        }
        __syncthreads();

#pragma unroll
        for (int ks = 0; ks < 2; ks++) {
            const int kb = it * GK + ks * 8;
            uint32_t ah[2][4], al[2][4];
#pragma unroll
            for (int m = 0; m < 2; m++) {
                int r0 = m * 16 + g;
                ah[m][0] = xsh[(r0)     * XS_PAD + kb + tq];
                ah[m][1] = xsh[(r0 + 8) * XS_PAD + kb + tq];
                ah[m][2] = xsh[(r0)     * XS_PAD + kb + tq + 4];
                ah[m][3] = xsh[(r0 + 8) * XS_PAD + kb + tq + 4];
                al[m][0] = xsl[(r0)     * XS_PAD + kb + tq];
                al[m][1] = xsl[(r0 + 8) * XS_PAD + kb + tq];
                al[m][2] = xsl[(r0)     * XS_PAD + kb + tq + 4];
                al[m][3] = xsl[(r0 + 8) * XS_PAD + kb + tq + 4];
            }
#pragma unroll
            for (int n = 0; n < 2; n++) {
                const int cb = wid * 16 + n * 8 + g;
                uint32_t bh0 = wbh[(ks * 8 + tq)     * WB_PAD + cb];
                uint32_t bh1 = wbh[(ks * 8 + tq + 4) * WB_PAD + cb];
                uint32_t bl0 = wbl[(ks * 8 + tq)     * WB_PAD + cb];
                uint32_t bl1 = wbl[(ks * 8 + tq + 4) * WB_PAD + cb];
#pragma unroll
                for (int m = 0; m < 2; m++) {
                    MMA_TF32(c[m][n], ah[m], bh0, bh1);   // hi*hi
                    MMA_TF32(c[m][n], ah[m], bl0, bl1);   // hi*lo
                    MMA_TF32(c[m][n], al[m], bh0, bh1);   // lo*hi
                }
            }
        }
        __syncthreads();
    }

    // epilogue: part[s][batch][col]
    float* op = part + (size_t)blockIdx.y * BATCH * ncols;
#pragma unroll
    for (int m = 0; m < 2; m++)
#pragma unroll
        for (int n = 0; n < 2; n++) {
            int row0 = m * 16 + g;
            int cb   = colbase + wid * 16 + n * 8 + 2 * tq;
            op[(size_t)row0 * ncols + cb]           = c[m][n][0];
            op[(size_t)row0 * ncols + cb + 1]       = c[m][n][1];
            op[(size_t)(row0 + 8) * ncols + cb]     = c[m][n][2];
            op[(size_t)(row0 + 8) * ncols + cb + 1] = c[m][n][3];
        }
}

// ----------------- reduce k-splits of QKV + RoPE + split q/k/v --------------
__global__ __launch_bounds__(256) void rope_reduce(const int* __restrict__ pos_ids) {
    int idx = blockIdx.x * 256 + threadIdx.x;
    int j  = idx & 63;
    int hh = (idx >> 6) % 48;
    int b  = idx / (48 * 64);

    int c1 = hh * HD + j;
    int c2 = c1 + 64;
    float x1 = 0.f, x2 = 0.f;
#pragma unroll
    for (int s = 0; s < KSPLIT; s++) {
        x1 += g_qkv_part[s][b][c1];
        x2 += g_qkv_part[s][b][c2];
    }
    if (hh < 40) {
        float invf = exp2f(-(float)j * (19.931568569324174f / 64.f)); // 1e6^(-j/64)
        float ang  = (float)pos_ids[b] * invf;
        float c = cosf(ang), s = sinf(ang);
        float y1 = x1 * c - x2 * s;
        float y2 = x2 * c + x1 * s;
        if (hh < 32) {
            const float sc = 0.08838834764831845f;   // 1/sqrt(128)
            g_q[b][hh][j]      = y1 * sc;
            g_q[b][hh][j + 64] = y2 * sc;
        } else {
            g_knew[b][hh - 32][j]      = y1;
            g_knew[b][hh - 32][j + 64] = y2;
        }
    } else {
        g_vnew[b][hh - 40][j]      = x1;
        g_vnew[b][hh - 40][j + 64] = x2;
    }
}

// -------- no-op spacer so the fixed ncu capture slot lands on attn_split ----
__global__ void prof_marker() {}

// ------------- per-warp two-phase split-KV flash-decode ----------------------
// (exact R6-best config: occ 2, unroll 2 / 8, in-loop new-token select)
__global__ __launch_bounds__(256, 2) void attn_split(const float* __restrict__ kc,
                                                     const float* __restrict__ vc,
                                                     const int* __restrict__ btab,
                                                     const int* __restrict__ seqlens) {
    const int s   = blockIdx.x;
    const int kvh = blockIdx.y;
    const int b   = blockIdx.z;

    __shared__ float4 ps4[8][PBLOCK];       // 8 KB: per-warp scores/probs (g-packed)
    __shared__ float  red[8][GSZ][HD];      // 16 KB: per-warp V partials
    __shared__ float  sm_m[8][GSZ], sm_l[8][GSZ];

    const int t    = threadIdx.x;
    const int w    = t >> 5;
    const int lane = t & 31;
    const int kvlen  = seqlens[b];
    const int newpos = kvlen - 1;

    const int phys = btab[b * NBLK + s * 8 + w];
    const int lsub = lane >> 3;      // octet index (position group)
    const int dch  = lane & 7;       // 16-dim chunk within octet

    const float* kblock = kc + ((size_t)phys * PBLOCK) * NKV * HD + (size_t)kvh * HD;
    const float* vblock = vc + ((size_t)phys * PBLOCK) * NKV * HD + (size_t)kvh * HD;
    const int base = s * SPLIT_LEN + w * 64;

    float mloc[GSZ];
    // ---------------- phase A: scores -> smem ----------------
    {
        F4 qr[GSZ][4];
#pragma unroll
        for (int g = 0; g < GSZ; g++) {
            const float4* qp = (const float4*)&g_q[b][kvh * GSZ + g][0];
#pragma unroll
            for (int q = 0; q < 4; q++) qr[g][q].f4 = qp[dch * 4 + q];
        }
#pragma unroll
        for (int g = 0; g < GSZ; g++) mloc[g] = -1e30f;

#pragma unroll 2
        for (int i = 0; i < 16; i++) {
            const int slot = i * 4 + lsub;
            const int gl = base + slot;
            const float* kp = kblock + (size_t)slot * NKV * HD;
            if (gl == newpos) kp = &g_knew[b][kvh][0];

            F4 kv[4];
#pragma unroll
            for (int q = 0; q < 4; q++) kv[q].f4 = __ldcs(((const float4*)kp) + dch * 4 + q);

            float sg[GSZ];
#pragma unroll
            for (int g = 0; g < GSZ; g++) {
                u64 a2 = 0ULL;
#pragma unroll
                for (int q = 0; q < 4; q++) {
                    a2 = ffma2(qr[g][q].u.lo, kv[q].u.lo, a2);
                    a2 = ffma2(qr[g][q].u.hi, kv[q].u.hi, a2);
                }
                float2 f = unpack2(a2);
                sg[g] = f.x + f.y;
            }
#pragma unroll
            for (int off = 1; off < 8; off <<= 1)
#pragma unroll
                for (int g = 0; g < GSZ; g++)
                    sg[g] += __shfl_xor_sync(0xffffffff, sg[g], off);

            if (dch == 0) {
                const bool valid = gl < kvlen;
                float4 sv;
                sv.x = valid ? sg[0] : -1e30f;
                sv.y = valid ? sg[1] : -1e30f;
                sv.z = valid ? sg[2] : -1e30f;
                sv.w = valid ? sg[3] : -1e30f;
                ps4[w][slot] = sv;
                mloc[0] = fmaxf(mloc[0], sv.x);
                mloc[1] = fmaxf(mloc[1], sv.y);
                mloc[2] = fmaxf(mloc[2], sv.z);
                mloc[3] = fmaxf(mloc[3], sv.w);
            }
        }
#pragma unroll
        for (int off = 16; off >= 1; off >>= 1)
#pragma unroll
            for (int g = 0; g < GSZ; g++)
                mloc[g] = fmaxf(mloc[g], __shfl_xor_sync(0xffffffff, mloc[g], off));
        __syncwarp();
    }

    // ---------------- phase B: exp + l ----------------
    {
        float4 s0 = ps4[w][lane];
        float4 s1 = ps4[w][lane + 32];
        float4 p0, p1;
        p0.x = __expf(s0.x - mloc[0]); p1.x = __expf(s1.x - mloc[0]);
        p0.y = __expf(s0.y - mloc[1]); p1.y = __expf(s1.y - mloc[1]);
        p0.z = __expf(s0.z - mloc[2]); p1.z = __expf(s1.z - mloc[2]);
        p0.w = __expf(s0.w - mloc[3]); p1.w = __expf(s1.w - mloc[3]);
        ps4[w][lane] = p0;
        ps4[w][lane + 32] = p1;
        float l0 = p0.x + p1.x, l1 = p0.y + p1.y;
        float l2 = p0.z + p1.z, l3 = p0.w + p1.w;
#pragma unroll
        for (int off = 16; off >= 1; off >>= 1) {
            l0 += __shfl_xor_sync(0xffffffff, l0, off);
            l1 += __shfl_xor_sync(0xffffffff, l1, off);
            l2 += __shfl_xor_sync(0xffffffff, l2, off);
            l3 += __shfl_xor_sync(0xffffffff, l3, off);
        }
        if (lane == 0) {
            sm_m[w][0] = mloc[0]; sm_m[w][1] = mloc[1];
            sm_m[w][2] = mloc[2]; sm_m[w][3] = mloc[3];
            sm_l[w][0] = l0; sm_l[w][1] = l1; sm_l[w][2] = l2; sm_l[w][3] = l3;
        }
        __syncwarp();
    }

    // -------- phase C: V stream, one position per iter, all lanes ----------
    {
        u64 acc2[GSZ][2];
#pragma unroll
        for (int g = 0; g < GSZ; g++) { acc2[g][0] = 0ULL; acc2[g][1] = 0ULL; }

#pragma unroll 8
        for (int slot = 0; slot < 64; slot++) {
            const int gl = base + slot;
            const float* vp = vblock + (size_t)slot * NKV * HD;
            if (gl == newpos) vp = &g_vnew[b][kvh][0];
            F4 v4;
            v4.f4 = __ldcs(((const float4*)vp) + lane);
            float4 p4 = ps4[w][slot];            // smem broadcast
            u64 pa = pack2(p4.x, p4.x);
            u64 pb = pack2(p4.y, p4.y);
            u64 pc = pack2(p4.z, p4.z);
            u64 pd = pack2(p4.w, p4.w);
            acc2[0][0] = ffma2(pa, v4.u.lo, acc2[0][0]);
            acc2[0][1] = ffma2(pa, v4.u.hi, acc2[0][1]);
            acc2[1][0] = ffma2(pb, v4.u.lo, acc2[1][0]);
            acc2[1][1] = ffma2(pb, v4.u.hi, acc2[1][1]);
            acc2[2][0] = ffma2(pc, v4.u.lo, acc2[2][0]);
            acc2[2][1] = ffma2(pc, v4.u.hi, acc2[2][1]);
            acc2[3][0] = ffma2(pd, v4.u.lo, acc2[3][0]);
            acc2[3][1] = ffma2(pd, v4.u.hi, acc2[3][1]);
        }
#pragma unroll
        for (int g = 0; g < GSZ; g++) {
            F4 o;
            o.u.lo = acc2[g][0];
            o.u.hi = acc2[g][1];
            ((float4*)&red[w][g][0])[lane] = o.f4;
        }
    }
    __syncthreads();

    // -------- epilogue: flash-merge the 8 warps' partials -> one ----------
#pragma unroll
    for (int rep = 0; rep < 2; rep++) {
        int idx = t + rep * 256;
        int g = idx >> 7, d = idx & 127;
        float M = sm_m[0][g];
#pragma unroll
        for (int ww = 1; ww < 8; ww++) M = fmaxf(M, sm_m[ww][g]);
        float o = 0.f;
#pragma unroll
        for (int ww = 0; ww < 8; ww++)
            o += __expf(sm_m[ww][g] - M) * red[ww][g][d];
        g_po[b][kvh][g][s][d] = o;
        if (d == 0) {
            float L = 0.f;
#pragma unroll
            for (int ww = 0; ww < 8; ww++)
                L += __expf(sm_m[ww][g] - M) * sm_l[ww][g];
            g_pm[b][kvh][g][s] = M;
            g_pl[b][kvh][g][s] = L;
        }
    }
}

// ----------------------- combine split partials -----------------------------
__global__ __launch_bounds__(128) void combine_splits() {
    const int bh = blockIdx.x;
    const int b = bh >> 5, h = bh & 31;
    const int kvh = h >> 2, g = h & 3;
    const int d = threadIdx.x;

    float m = -1e30f;
#pragma unroll
    for (int s = 0; s < NSUB; s++) m = fmaxf(m, g_pm[b][kvh][g][s]);
    float denom = 0.f, o = 0.f;
#pragma unroll
    for (int s = 0; s < NSUB; s++) {
        float e = __expf(g_pm[b][kvh][g][s] - m);
        denom += e * g_pl[b][kvh][g][s];
        o += e * g_po[b][kvh][g][s][d];
    }
    g_attn[b][h * HD + d] = o / denom;
}

// ----------------------- final k-split reduce -------------------------------
__global__ __launch_bounds__(256) void final_reduce(float* __restrict__ out) {
    int e = blockIdx.x * 256 + threadIdx.x;        // over 32*4096
    const float* p = &g_out_part[0][0][0];
    float sum = 0.f;
#pragma unroll
    for (int s = 0; s < KSPLIT; s++) sum += p[(size_t)s * BATCH * DMODEL + e];
    out[e] = sum;
}

// ---------------------------------------------------------------------------
extern "C" void kernel_launch(void* const* d_in, const int* in_sizes, int n_in,
                              void* d_out, int out_size) {
    const float* hid  = (const float*)d_in[0];
    const float* wqkv = (const float*)d_in[1];
    const float* wo   = (const float*)d_in[2];
    const float* kc   = (const float*)d_in[3];
    const float* vc   = (const float*)d_in[4];
    const int*   pos  = (const int*)d_in[5];
    const int*   btab = (const int*)d_in[6];
    const int*   slen = (const int*)d_in[7];
    float* out = (float*)d_out;

    void *p_qkv_part, *p_attn, *p_out_part;
    cudaGetSymbolAddress(&p_qkv_part, g_qkv_part);
    cudaGetSymbolAddress(&p_attn, g_attn);
    cudaGetSymbolAddress(&p_out_part, g_out_part);

    const int gemm_smem = (2 * 32 * XS_PAD + 2 * GK * WB_PAD) * 4;   // 82688 B
    cudaFuncSetAttribute(gemm_tf32, cudaFuncAttributeMaxDynamicSharedMemorySize,
                         gemm_smem);

    gemm_tf32<<<dim3(QKV_COLS / 128, KSPLIT), 256, gemm_smem>>>(hid, wqkv,
                                                    (float*)p_qkv_part, QKV_COLS);
    rope_reduce<<<(BATCH * 48 * 64) / 256, 256>>>(pos);
    prof_marker<<<1, 32>>>();
    attn_split<<<dim3(SPLITS, NKV, BATCH), 256>>>(kc, vc, btab, slen);
    combine_splits<<<BATCH * NH, 128>>>();
    gemm_tf32<<<dim3(DMODEL / 128, KSPLIT), 256, gemm_smem>>>((const float*)p_attn,
                                                    wo, (float*)p_out_part, DMODEL);
    final_reduce<<<(BATCH * DMODEL) / 256, 256>>>(out);
}

// round 14
// speedup vs baseline: 1.2849x; 1.1088x over previous
#include <cuda_runtime.h>
#include <cuda_bf16.h>
#include <math.h>
#include <stdint.h>

#define BATCH   32
#define DMODEL  4096
#define NH      32
#define NKV     8
#define GSZ     4          // NH / NKV
#define HD      128
#define QKV_COLS 6144      // (NH + 2*NKV) * HD
#define PBLOCK  64
#define NBLK    64
#define SPLITS  8
#define SPLIT_LEN 512      // 4096 / SPLITS
#define NSUB    SPLITS     // per-CTA merged partials
#define KSPLIT  16
#define KCHUNK  256        // 4096 / KSPLIT
#define GKB     32         // gemm k rows per tile (2 x k16 mma steps)
#define XPAD    132        // xs row pitch (uint32) — conflict-free fragment LDS
#define WPAD    20         // wb col pitch (uint32) — conflict-free fragment LDS

typedef unsigned long long u64;

// -------------------- packed f32x2 helpers (sm_100+) ------------------------
__device__ __forceinline__ u64 ffma2(u64 a, u64 b, u64 c) {
    u64 d;
    asm("fma.rn.f32x2 %0, %1, %2, %3;" : "=l"(d) : "l"(a), "l"(b), "l"(c));
    return d;
}
__device__ __forceinline__ u64 pack2(float lo, float hi) {
    u64 r;
    asm("mov.b64 %0, {%1, %2};" : "=l"(r) : "f"(lo), "f"(hi));
    return r;
}
__device__ __forceinline__ float2 unpack2(u64 v) {
    float2 f;
    asm("mov.b64 {%0, %1}, %2;" : "=f"(f.x), "=f"(f.y) : "l"(v));
    return f;
}
union F4 {
    float4 f4;
    struct { u64 lo, hi; } u;
};

// ---------------- bf16 hi/lo split, packed as bf16x2 (lo half = even k) -----
__device__ __forceinline__ void bf16_split2(float fe, float fo,
                                            uint32_t& h, uint32_t& l) {
    uint32_t hh;
    asm("cvt.rn.bf16x2.f32 %0, %1, %2;" : "=r"(hh) : "f"(fo), "f"(fe));
    float rfe = fe - __uint_as_float(hh << 16);
    float rfo = fo - __uint_as_float(hh & 0xffff0000u);
    uint32_t ll;
    asm("cvt.rn.bf16x2.f32 %0, %1, %2;" : "=r"(ll) : "f"(rfo), "f"(rfe));
    h = hh; l = ll;
}

#define MMA_BF16(C, A, b0, b1)                                              \
    asm volatile("mma.sync.aligned.m16n8k16.row.col.f32.bf16.bf16.f32 "     \
                 "{%0,%1,%2,%3}, {%4,%5,%6,%7}, {%8,%9}, {%0,%1,%2,%3};"    \
                 : "+f"((C)[0]), "+f"((C)[1]), "+f"((C)[2]), "+f"((C)[3])   \
                 : "r"((A)[0]), "r"((A)[1]), "r"((A)[2]), "r"((A)[3]),      \
                   "r"(b0), "r"(b1))

// ------------------------------ scratch -------------------------------------
__device__ float g_qkv_part[KSPLIT][BATCH][QKV_COLS];   // 12.6 MB
__device__ float g_q[BATCH][NH][HD];                    // prescaled by 1/sqrt(HD)
__device__ float g_knew[BATCH][NKV][HD];
__device__ float g_vnew[BATCH][NKV][HD];
__device__ float g_po[BATCH][NKV][GSZ][NSUB][HD];       // 4.2 MB
__device__ float g_pm[BATCH][NKV][GSZ][NSUB];
__device__ float g_pl[BATCH][NKV][GSZ][NSUB];
__device__ float g_attn[BATCH][NH * HD];
__device__ float g_out_part[KSPLIT][BATCH][DMODEL];     // 8.4 MB

// --------- bf16x3 tensor-core 32-row GEMM:  part[s] = x_chunk @ w_chunk -----
// Error-compensated: x,w split into bf16 hi+lo; accumulate hihi + hilo + lohi.
// grid: (ncols/128, KSPLIT), block 256 (8 warps, 16 cols each).
// smem: xs hi/lo [32][XPAD] packed bf16x2 kpairs + w tile hi/lo [128][WPAD].
__global__ __launch_bounds__(256) void gemm_bf16x3(const float* __restrict__ x,
                                                   const float* __restrict__ w,
                                                   float* __restrict__ part,
                                                   int ncols) {
    extern __shared__ uint32_t dyn[];
    uint32_t* xsh = dyn;                        // 32*XPAD
    uint32_t* xsl = xsh + 32 * XPAD;
    uint32_t* wbh = xsl + 32 * XPAD;            // 128*WPAD (col-major: [col][kpair])
    uint32_t* wbl = wbh + 128 * WPAD;

    const int t    = threadIdx.x;
    const int wid  = t >> 5;
    const int lane = t & 31;
    const int g    = lane >> 2;     // groupID 0..7
    const int tq   = lane & 3;      // threadID-in-group 0..3
    const int colbase = blockIdx.x * 128;
    const int k0      = blockIdx.y * KCHUNK;

    // ---- stage x chunk once: [32][K=256] -> packed bf16x2 kpairs hi/lo ----
    for (int i = t; i < 32 * (KCHUNK / 4); i += 256) {
        int row = i >> 6;
        int kk  = (i & 63) * 4;
        float4 v = *(const float4*)(x + (size_t)row * DMODEL + k0 + kk);
        uint32_t h, l;
        bf16_split2(v.x, v.y, h, l);
        xsh[row * XPAD + (kk >> 1)]     = h;
        xsl[row * XPAD + (kk >> 1)]     = l;
        bf16_split2(v.z, v.w, h, l);
        xsh[row * XPAD + (kk >> 1) + 1] = h;
        xsl[row * XPAD + (kk >> 1) + 1] = l;
    }

    float c[2][2][4];
#pragma unroll
    for (int m = 0; m < 2; m++)
#pragma unroll
        for (int n = 0; n < 2; n++)
#pragma unroll
            for (int j = 0; j < 4; j++) c[m][n][j] = 0.f;

    for (int it = 0; it < KCHUNK / GKB; it++) {      // 8 iterations
        __syncthreads();   // prev tile consumed (and x staging visible at it=0)

        // ---- stage w tile [GKB=32 rows][128 cols] transposed hi/lo ----
#pragma unroll
        for (int rep = 0; rep < 2; rep++) {
            int tau = t + rep * 256;
            int kp  = tau >> 5;            // kpair 0..15
            int cc  = (tau & 31) * 4;      // col 0..124
            const float* wp = w + (size_t)(k0 + it * GKB + 2 * kp) * ncols
                                + colbase + cc;
            float4 r0 = *(const float4*)wp;
            float4 r1 = *(const float4*)(wp + ncols);
            uint32_t h, l;
            bf16_split2(r0.x, r1.x, h, l);
            wbh[(cc + 0) * WPAD + kp] = h;  wbl[(cc + 0) * WPAD + kp] = l;
            bf16_split2(r0.y, r1.y, h, l);
            wbh[(cc + 1) * WPAD + kp] = h;  wbl[(cc + 1) * WPAD + kp] = l;
            bf16_split2(r0.z, r1.z, h, l);
            wbh[(cc + 2) * WPAD + kp] = h;  wbl[(cc + 2) * WPAD + kp] = l;
            bf16_split2(r0.w, r1.w, h, l);
            wbh[(cc + 3) * WPAD + kp] = h;  wbl[(cc + 3) * WPAD + kp] = l;
        }
        __syncthreads();

#pragma unroll
        for (int ks = 0; ks < 2; ks++) {
            const int kc = it * 16 + 8 * ks;   // kpair column base in xs
            uint32_t ah[2][4], al[2][4];
#pragma unroll
            for (int m = 0; m < 2; m++) {
                int r0 = m * 16 + g;
                ah[m][0] = xsh[(r0)     * XPAD + kc + tq];
                ah[m][1] = xsh[(r0 + 8) * XPAD + kc + tq];
                ah[m][2] = xsh[(r0)     * XPAD + kc + tq + 4];
                ah[m][3] = xsh[(r0 + 8) * XPAD + kc + tq + 4];
                al[m][0] = xsl[(r0)     * XPAD + kc + tq];
                al[m][1] = xsl[(r0 + 8) * XPAD + kc + tq];
                al[m][2] = xsl[(r0)     * XPAD + kc + tq + 4];
                al[m][3] = xsl[(r0 + 8) * XPAD + kc + tq + 4];
            }
#pragma unroll
            for (int n = 0; n < 2; n++) {
                const int cb = wid * 16 + n * 8 + g;
                uint32_t bh0 = wbh[cb * WPAD + 8 * ks + tq];
                uint32_t bh1 = wbh[cb * WPAD + 8 * ks + tq + 4];
                uint32_t bl0 = wbl[cb * WPAD + 8 * ks + tq];
                uint32_t bl1 = wbl[cb * WPAD + 8 * ks + tq + 4];
#pragma unroll
                for (int m = 0; m < 2; m++) {
                    MMA_BF16(c[m][n], ah[m], bh0, bh1);   // hi*hi
                    MMA_BF16(c[m][n], ah[m], bl0, bl1);   // hi*lo
                    MMA_BF16(c[m][n], al[m], bh0, bh1);   // lo*hi
                }
            }
        }
    }

    // epilogue: part[s][batch][col]
    float* op = part + (size_t)blockIdx.y * BATCH * ncols;
#pragma unroll
    for (int m = 0; m < 2; m++)
#pragma unroll
        for (int n = 0; n < 2; n++) {
            int row0 = m * 16 + g;
            int cb   = colbase + wid * 16 + n * 8 + 2 * tq;
            op[(size_t)row0 * ncols + cb]           = c[m][n][0];
            op[(size_t)row0 * ncols + cb + 1]       = c[m][n][1];
            op[(size_t)(row0 + 8) * ncols + cb]     = c[m][n][2];
            op[(size_t)(row0 + 8) * ncols + cb + 1] = c[m][n][3];
        }
}

// ----------------- reduce k-splits of QKV + RoPE + split q/k/v --------------
__global__ __launch_bounds__(256) void rope_reduce(const int* __restrict__ pos_ids) {
    int idx = blockIdx.x * 256 + threadIdx.x;
    int j  = idx & 63;
    int hh = (idx >> 6) % 48;
    int b  = idx / (48 * 64);

    int c1 = hh * HD + j;
    int c2 = c1 + 64;
    float x1 = 0.f, x2 = 0.f;
#pragma unroll
    for (int s = 0; s < KSPLIT; s++) {
        x1 += g_qkv_part[s][b][c1];
        x2 += g_qkv_part[s][b][c2];
    }
    if (hh < 40) {
        float invf = exp2f(-(float)j * (19.931568569324174f / 64.f)); // 1e6^(-j/64)
        float ang  = (float)pos_ids[b] * invf;
        float c = cosf(ang), s = sinf(ang);
        float y1 = x1 * c - x2 * s;
        float y2 = x2 * c + x1 * s;
        if (hh < 32) {
            const float sc = 0.08838834764831845f;   // 1/sqrt(128)
            g_q[b][hh][j]      = y1 * sc;
            g_q[b][hh][j + 64] = y2 * sc;
        } else {
            g_knew[b][hh - 32][j]      = y1;
            g_knew[b][hh - 32][j + 64] = y2;
        }
    } else {
        g_vnew[b][hh - 40][j]      = x1;
        g_vnew[b][hh - 40][j + 64] = x2;
    }
}

// -------- no-op spacer so the fixed ncu capture slot lands on gemm #2 -------
__global__ void prof_marker() {}

// ------------- per-warp two-phase split-KV flash-decode ----------------------
// (exact R6-best config: occ 2, unroll 2 / 8, in-loop new-token select)
__global__ __launch_bounds__(256, 2) void attn_split(const float* __restrict__ kc,
                                                     const float* __restrict__ vc,
                                                     const int* __restrict__ btab,
                                                     const int* __restrict__ seqlens) {
    const int s   = blockIdx.x;
    const int kvh = blockIdx.y;
    const int b   = blockIdx.z;

    __shared__ float4 ps4[8][PBLOCK];       // 8 KB: per-warp scores/probs (g-packed)
    __shared__ float  red[8][GSZ][HD];      // 16 KB: per-warp V partials
    __shared__ float  sm_m[8][GSZ], sm_l[8][GSZ];

    const int t    = threadIdx.x;
    const int w    = t >> 5;
    const int lane = t & 31;
    const int kvlen  = seqlens[b];
    const int newpos = kvlen - 1;

    const int phys = btab[b * NBLK + s * 8 + w];
    const int lsub = lane >> 3;      // octet index (position group)
    const int dch  = lane & 7;       // 16-dim chunk within octet

    const float* kblock = kc + ((size_t)phys * PBLOCK) * NKV * HD + (size_t)kvh * HD;
    const float* vblock = vc + ((size_t)phys * PBLOCK) * NKV * HD + (size_t)kvh * HD;
    const int base = s * SPLIT_LEN + w * 64;

    float mloc[GSZ];
    // ---------------- phase A: scores -> smem ----------------
    {
        F4 qr[GSZ][4];
#pragma unroll
        for (int g = 0; g < GSZ; g++) {
            const float4* qp = (const float4*)&g_q[b][kvh * GSZ + g][0];
#pragma unroll
            for (int q = 0; q < 4; q++) qr[g][q].f4 = qp[dch * 4 + q];
        }
#pragma unroll
        for (int g = 0; g < GSZ; g++) mloc[g] = -1e30f;

#pragma unroll 2
        for (int i = 0; i < 16; i++) {
            const int slot = i * 4 + lsub;
            const int gl = base + slot;
            const float* kp = kblock + (size_t)slot * NKV * HD;
            if (gl == newpos) kp = &g_knew[b][kvh][0];

            F4 kv[4];
#pragma unroll
            for (int q = 0; q < 4; q++) kv[q].f4 = __ldcs(((const float4*)kp) + dch * 4 + q);

            float sg[GSZ];
#pragma unroll
            for (int g = 0; g < GSZ; g++) {
                u64 a2 = 0ULL;
#pragma unroll
                for (int q = 0; q < 4; q++) {
                    a2 = ffma2(qr[g][q].u.lo, kv[q].u.lo, a2);
                    a2 = ffma2(qr[g][q].u.hi, kv[q].u.hi, a2);
                }
                float2 f = unpack2(a2);
                sg[g] = f.x + f.y;
            }
#pragma unroll
            for (int off = 1; off < 8; off <<= 1)
#pragma unroll
                for (int g = 0; g < GSZ; g++)
                    sg[g] += __shfl_xor_sync(0xffffffff, sg[g], off);

            if (dch == 0) {
                const bool valid = gl < kvlen;
                float4 sv;
                sv.x = valid ? sg[0] : -1e30f;
                sv.y = valid ? sg[1] : -1e30f;
                sv.z = valid ? sg[2] : -1e30f;
                sv.w = valid ? sg[3] : -1e30f;
                ps4[w][slot] = sv;
                mloc[0] = fmaxf(mloc[0], sv.x);
                mloc[1] = fmaxf(mloc[1], sv.y);
                mloc[2] = fmaxf(mloc[2], sv.z);
                mloc[3] = fmaxf(mloc[3], sv.w);
            }
        }
#pragma unroll
        for (int off = 16; off >= 1; off >>= 1)
#pragma unroll
            for (int g = 0; g < GSZ; g++)
                mloc[g] = fmaxf(mloc[g], __shfl_xor_sync(0xffffffff, mloc[g], off));
        __syncwarp();
    }

    // ---------------- phase B: exp + l ----------------
    {
        float4 s0 = ps4[w][lane];
        float4 s1 = ps4[w][lane + 32];
        float4 p0, p1;
        p0.x = __expf(s0.x - mloc[0]); p1.x = __expf(s1.x - mloc[0]);
        p0.y = __expf(s0.y - mloc[1]); p1.y = __expf(s1.y - mloc[1]);
        p0.z = __expf(s0.z - mloc[2]); p1.z = __expf(s1.z - mloc[2]);
        p0.w = __expf(s0.w - mloc[3]); p1.w = __expf(s1.w - mloc[3]);
        ps4[w][lane] = p0;
        ps4[w][lane + 32] = p1;
        float l0 = p0.x + p1.x, l1 = p0.y + p1.y;
        float l2 = p0.z + p1.z, l3 = p0.w + p1.w;
#pragma unroll
        for (int off = 16; off >= 1; off >>= 1) {
            l0 += __shfl_xor_sync(0xffffffff, l0, off);
            l1 += __shfl_xor_sync(0xffffffff, l1, off);
            l2 += __shfl_xor_sync(0xffffffff, l2, off);
            l3 += __shfl_xor_sync(0xffffffff, l3, off);
        }
        if (lane == 0) {
            sm_m[w][0] = mloc[0]; sm_m[w][1] = mloc[1];
            sm_m[w][2] = mloc[2]; sm_m[w][3] = mloc[3];
            sm_l[w][0] = l0; sm_l[w][1] = l1; sm_l[w][2] = l2; sm_l[w][3] = l3;
        }
        __syncwarp();
    }

    // -------- phase C: V stream, one position per iter, all lanes ----------
    {
        u64 acc2[GSZ][2];
#pragma unroll
        for (int g = 0; g < GSZ; g++) { acc2[g][0] = 0ULL; acc2[g][1] = 0ULL; }

#pragma unroll 8
        for (int slot = 0; slot < 64; slot++) {
            const int gl = base + slot;
            const float* vp = vblock + (size_t)slot * NKV * HD;
            if (gl == newpos) vp = &g_vnew[b][kvh][0];
            F4 v4;
            v4.f4 = __ldcs(((const float4*)vp) + lane);
            float4 p4 = ps4[w][slot];            // smem broadcast
            u64 pa = pack2(p4.x, p4.x);
            u64 pb = pack2(p4.y, p4.y);
            u64 pc = pack2(p4.z, p4.z);
            u64 pd = pack2(p4.w, p4.w);
            acc2[0][0] = ffma2(pa, v4.u.lo, acc2[0][0]);
            acc2[0][1] = ffma2(pa, v4.u.hi, acc2[0][1]);
            acc2[1][0] = ffma2(pb, v4.u.lo, acc2[1][0]);
            acc2[1][1] = ffma2(pb, v4.u.hi, acc2[1][1]);
            acc2[2][0] = ffma2(pc, v4.u.lo, acc2[2][0]);
            acc2[2][1] = ffma2(pc, v4.u.hi, acc2[2][1]);
            acc2[3][0] = ffma2(pd, v4.u.lo, acc2[3][0]);
            acc2[3][1] = ffma2(pd, v4.u.hi, acc2[3][1]);
        }
#pragma unroll
        for (int g = 0; g < GSZ; g++) {
            F4 o;
            o.u.lo = acc2[g][0];
            o.u.hi = acc2[g][1];
            ((float4*)&red[w][g][0])[lane] = o.f4;
        }
    }
    __syncthreads();

    // -------- epilogue: flash-merge the 8 warps' partials -> one ----------
#pragma unroll
    for (int rep = 0; rep < 2; rep++) {
        int idx = t + rep * 256;
        int g = idx >> 7, d = idx & 127;
        float M = sm_m[0][g];
#pragma unroll
        for (int ww = 1; ww < 8; ww++) M = fmaxf(M, sm_m[ww][g]);
        float o = 0.f;
#pragma unroll
        for (int ww = 0; ww < 8; ww++)
            o += __expf(sm_m[ww][g] - M) * red[ww][g][d];
        g_po[b][kvh][g][s][d] = o;
        if (d == 0) {
            float L = 0.f;
#pragma unroll
            for (int ww = 0; ww < 8; ww++)
                L += __expf(sm_m[ww][g] - M) * sm_l[ww][g];
            g_pm[b][kvh][g][s] = M;
            g_pl[b][kvh][g][s] = L;
        }
    }
}

// ----------------------- combine split partials -----------------------------
__global__ __launch_bounds__(128) void combine_splits() {
    const int bh = blockIdx.x;
    const int b = bh >> 5, h = bh & 31;
    const int kvh = h >> 2, g = h & 3;
    const int d = threadIdx.x;

    float m = -1e30f;
#pragma unroll
    for (int s = 0; s < NSUB; s++) m = fmaxf(m, g_pm[b][kvh][g][s]);
    float denom = 0.f, o = 0.f;
#pragma unroll
    for (int s = 0; s < NSUB; s++) {
        float e = __expf(g_pm[b][kvh][g][s] - m);
        denom += e * g_pl[b][kvh][g][s];
        o += e * g_po[b][kvh][g][s][d];
    }
    g_attn[b][h * HD + d] = o / denom;
}

// ----------------------- final k-split reduce -------------------------------
__global__ __launch_bounds__(256) void final_reduce(float* __restrict__ out) {
    int e = blockIdx.x * 256 + threadIdx.x;        // over 32*4096
    const float* p = &g_out_part[0][0][0];
    float sum = 0.f;
#pragma unroll
    for (int s = 0; s < KSPLIT; s++) sum += p[(size_t)s * BATCH * DMODEL + e];
    out[e] = sum;
}

// ---------------------------------------------------------------------------
extern "C" void kernel_launch(void* const* d_in, const int* in_sizes, int n_in,
                              void* d_out, int out_size) {
    const float* hid  = (const float*)d_in[0];
    const float* wqkv = (const float*)d_in[1];
    const float* wo   = (const float*)d_in[2];
    const float* kc   = (const float*)d_in[3];
    const float* vc   = (const float*)d_in[4];
    const int*   pos  = (const int*)d_in[5];
    const int*   btab = (const int*)d_in[6];
    const int*   slen = (const int*)d_in[7];
    float* out = (float*)d_out;

    void *p_qkv_part, *p_attn, *p_out_part;
    cudaGetSymbolAddress(&p_qkv_part, g_qkv_part);
    cudaGetSymbolAddress(&p_attn, g_attn);
    cudaGetSymbolAddress(&p_out_part, g_out_part);

    const int gemm_smem = (2 * 32 * XPAD + 2 * 128 * WPAD) * 4;   // 54272 B
    cudaFuncSetAttribute(gemm_bf16x3, cudaFuncAttributeMaxDynamicSharedMemorySize,
                         gemm_smem);

    gemm_bf16x3<<<dim3(QKV_COLS / 128, KSPLIT), 256, gemm_smem>>>(hid, wqkv,
                                                    (float*)p_qkv_part, QKV_COLS);
    rope_reduce<<<(BATCH * 48 * 64) / 256, 256>>>(pos);
    attn_split<<<dim3(SPLITS, NKV, BATCH), 256>>>(kc, vc, btab, slen);
    combine_splits<<<BATCH * NH, 128>>>();
    prof_marker<<<1, 32>>>();
    gemm_bf16x3<<<dim3(DMODEL / 128, KSPLIT), 256, gemm_smem>>>((const float*)p_attn,
                                                    wo, (float*)p_out_part, DMODEL);
    final_reduce<<<(BATCH * DMODEL) / 256, 256>>>(out);
}